// round 17
// baseline (speedup 1.0000x reference)
#include <cuda_runtime.h>
#include <cuda_bf16.h>

// S4 Vandermonde kernel via warp-level bf16 mma.sync.
//   out[h, 64a+b] = sum_k G[a,k] * V[b,k],   K = 64 (re/im of 32 modes)
// fp32 accuracy via Dekker bf16 splits: D = G1V1 + G1V2 + G2V1.
// R16 vs R15:
//  (1) __launch_bounds__(128,4): 592 concurrent CTA slots >= 512 -> ONE wave
//      (R15's occ-3 left a 68-CTA serial tail).
//  (2) V fragments (mode n, col b) are h-dependent but WARP-INDEPENDENT:
//      generated once per CTA into smem tables (pitch 72 words -> LDS index
//      mod 32 = 8t+g+8j, bijective per warp = conflict-free), killing the
//      4x redundant per-warp V generation (~576 inst/warp).

typedef unsigned int u32;

#define HH 512
#define NH 32
#define LL 8192
#define VP 72                      // V table row pitch in words (bank-bijective)

#define PI2_HI 6.2831854820251465f
#define PI2_LO (-1.7484561e-7f)
#define INV2PI 0.15915494309189535f

__device__ __forceinline__ void redsc(float th, float* s, float* c) {
    float kk = rintf(th * INV2PI);
    float r  = fmaf(-kk, PI2_HI, th);
    r        = fmaf(-kk, PI2_LO, r);
    __sincosf(r, s, c);
}
__device__ __forceinline__ float2 cmulf(float2 a, float2 b) {
    return make_float2(fmaf(a.x, b.x, -a.y * b.y), fmaf(a.x, b.y, a.y * b.x));
}
__device__ __forceinline__ u32 pack_split(float x, float y, float& rx, float& ry) {
    u32 w; asm("cvt.rn.bf16x2.f32 %0, %1, %2;" : "=r"(w) : "f"(y), "f"(x));
    rx = x - __uint_as_float(w << 16);
    ry = y - __uint_as_float(w & 0xFFFF0000u);
    return w;
}
__device__ __forceinline__ u32 pack_only(float x, float y) {
    u32 w; asm("cvt.rn.bf16x2.f32 %0, %1, %2;" : "=r"(w) : "f"(y), "f"(x));
    return w;
}
__device__ __forceinline__ void mma_bf16(float* c, u32 a0, u32 a1, u32 a2, u32 a3,
                                         u32 b0, u32 b1) {
    asm volatile(
        "mma.sync.aligned.m16n8k16.row.col.f32.bf16.bf16.f32 "
        "{%0,%1,%2,%3}, {%4,%5,%6,%7}, {%8,%9}, {%0,%1,%2,%3};"
        : "+f"(c[0]), "+f"(c[1]), "+f"(c[2]), "+f"(c[3])
        : "r"(a0), "r"(a1), "r"(a2), "r"(a3), "r"(b0), "r"(b1));
}

__global__ void __launch_bounds__(128, 4)
s4_mma_kernel(const float* __restrict__ log_dt,
              const float* __restrict__ log_A_real,
              const float* __restrict__ A_imag,
              const float* __restrict__ Bmat,
              const float* __restrict__ Cmat,
              float* __restrict__ out)
{
    __shared__ float4 prm[NH];           // {dre, dim, c2r, c2i}, c2 = 2*Ceff
    __shared__ u32 Vhi[NH * VP];         // V hi bf16x2, indexed [n*VP + b]
    __shared__ u32 Vlo[NH * VP];         // V residual bf16x2
    const int tid = threadIdx.x, wid = tid >> 5, lid = tid & 31;
    const int g = lid >> 2, t = lid & 3;
    const int h = blockIdx.x;

    // ---- mode params (warp 0, lane n) ----
    if (wid == 0) {
        const int n = lid;
        float dt  = __expf(log_dt[h]);
        float ar  = -__expf(log_A_real[h * NH + n]);
        float aiv = -A_imag[h * NH + n];
        float dre = dt * ar, dim = dt * aiv;
        float s1, c1; redsc(dim, &s1, &c1);
        float mg1 = __expf(dre);
        float2 w1  = make_float2(mg1 * c1, mg1 * s1);
        float2 num = make_float2(w1.x - 1.0f, w1.y);
        float  inv = 2.0f / fmaf(ar, ar, aiv * aiv);
        float2 ia  = make_float2(ar * inv, -aiv * inv);
        const float2* Bv = (const float2*)Bmat;
        const float2* Cv = (const float2*)Cmat;
        float2 bc = cmulf(Bv[h * NH + n], Cv[h * NH + n]);
        float2 c2 = cmulf(cmulf(bc, num), ia);
        prm[n] = make_float4(dre, dim, c2.x, c2.y);
    }
    __syncthreads();

    // ---- cooperative V generation: warp w owns modes 8w..8w+7, lane owns
    //      b = lid and lid+32; direct eval w^b = exp(dre*b)*(cos,sin)(dim*b) ----
    #pragma unroll
    for (int m = 0; m < 8; m++) {
        const int n = 8 * wid + m;
        const float4 p = prm[n];
        #pragma unroll
        for (int half = 0; half < 2; half++) {
            const int b = lid + 32 * half;
            float lb = (float)b;
            float sn, cs; redsc(p.y * lb, &sn, &cs);
            float mg = __expf(p.x * lb);
            float vr = mg * cs, vi = mg * sn;
            float rr, ri;
            u32 w1 = pack_split(vr, vi, rr, ri);
            Vhi[n * VP + b] = w1;
            Vlo[n * VP + b] = pack_only(rr, ri);
        }
    }
    __syncthreads();

    // ---- accumulators ----
    float acc[2][8][4];
    #pragma unroll
    for (int mt = 0; mt < 2; mt++)
        #pragma unroll
        for (int nt = 0; nt < 8; nt++)
            #pragma unroll
            for (int r = 0; r < 4; r++) acc[mt][nt][r] = 0.0f;

    #pragma unroll 1
    for (int ks = 0; ks < 4; ks++) {
        u32 ahi[2][4], alo[2][4], bhi[2][8], blo[2][8];
        #pragma unroll
        for (int mh = 0; mh < 2; mh++) {
            const int n = 8 * ks + t + 4 * mh;
            const float4 p = prm[n];

            // ---- A (G) rows a_i = 32*wid + g + 8*i, l = 64*a ----
            {
                float la = (float)((32 * wid + g) * 64);
                float sn, cs; redsc(p.y * la, &sn, &cs);
                float mg = __expf(p.x * la);
                float zr = mg * cs, zi = mg * sn;
                float cr = fmaf(p.z, zr, -p.w * zi);  // G = 2Ceff * w^l
                float ci = fmaf(p.z, zi,  p.w * zr);
                float ss, sc2; redsc(p.y * 512.0f, &ss, &sc2);
                float smg = __expf(p.x * 512.0f);     // w^512 row step
                float wr = smg * sc2, wi = smg * ss;
                #pragma unroll
                for (int i = 0; i < 4; i++) {
                    float rr, ri;
                    ahi[mh][i] = pack_split(cr, -ci, rr, ri);  // (Re, -Im)
                    alo[mh][i] = pack_only(rr, ri);
                    float nr = fmaf(cr, wr, -ci * wi);
                    float ni = fmaf(cr, wi,  ci * wr);
                    cr = nr; ci = ni;
                }
            }
            // ---- B (V) from shared tables: col b = g + 8*j ----
            {
                const u32* vh = &Vhi[n * VP + g];
                const u32* vl = &Vlo[n * VP + g];
                #pragma unroll
                for (int j = 0; j < 8; j++) {
                    bhi[mh][j] = vh[8 * j];
                    blo[mh][j] = vl[8 * j];
                }
            }
        }
        // ---- 48 MMAs: 2 m-tiles x 8 n-tiles x 3 split terms ----
        #pragma unroll
        for (int mt = 0; mt < 2; mt++) {
            #pragma unroll
            for (int nt = 0; nt < 8; nt++) {
                mma_bf16(acc[mt][nt],
                         ahi[0][2 * mt], ahi[0][2 * mt + 1],
                         ahi[1][2 * mt], ahi[1][2 * mt + 1],
                         bhi[0][nt], bhi[1][nt]);              // G1*V1
                mma_bf16(acc[mt][nt],
                         ahi[0][2 * mt], ahi[0][2 * mt + 1],
                         ahi[1][2 * mt], ahi[1][2 * mt + 1],
                         blo[0][nt], blo[1][nt]);              // G1*V2
                mma_bf16(acc[mt][nt],
                         alo[0][2 * mt], alo[0][2 * mt + 1],
                         alo[1][2 * mt], alo[1][2 * mt + 1],
                         bhi[0][nt], bhi[1][nt]);              // G2*V1
            }
        }
    }

    // ---- store: D[a][b] -> out[h, 64a + b] ----
    float* ob = out + h * LL;
    #pragma unroll
    for (int mt = 0; mt < 2; mt++) {
        const int a0r = 32 * wid + 16 * mt + g;
        #pragma unroll
        for (int nt = 0; nt < 8; nt++) {
            const int bc = 8 * nt + 2 * t;
            *(float2*)(ob + a0r * 64 + bc) =
                make_float2(acc[mt][nt][0], acc[mt][nt][1]);
            *(float2*)(ob + (a0r + 8) * 64 + bc) =
                make_float2(acc[mt][nt][2], acc[mt][nt][3]);
        }
    }
}

extern "C" void kernel_launch(void* const* d_in, const int* in_sizes, int n_in,
                              void* d_out, int out_size)
{
    const float* log_dt     = (const float*)d_in[0];
    const float* log_A_real = (const float*)d_in[1];
    const float* A_imag     = (const float*)d_in[2];
    const float* Bmat       = (const float*)d_in[3];
    const float* Cmat       = (const float*)d_in[4];
    float* out = (float*)d_out;

    s4_mma_kernel<<<HH, 128>>>(log_dt, log_A_real, A_imag, Bmat, Cmat, out);
}